// round 14
// baseline (speedup 1.0000x reference)
#include <cuda_runtime.h>
#include <cuda_bf16.h>

// 6-level cascaded db4 DWT, zero-padding, fully fused.
// Dense-load + warp-shuffle-halo scheme: each thread computes an output pair
// (j0, j0+1) and loads ONLY its own 4 dense input floats (one LDS/LDG.128,
// dense across the warp); the 6 halo floats come from neighbor lanes via
// __shfl. Warp-edge lanes patch with direct loads. Loop bounds are padded to
// warp multiples so shuffles are full-warp; out-of-range lanes load in-bounds
// (smem, padded buffers) or guarded-zero (gmem), and their results are
// discarded by the store predicate. Stores are merged float2 when the row
// base is 8B-aligned (always for even-LEN levels; per-row parity for d1/d2).
//
// Zero-pad invariant: any slot with global index outside [0,LEN) computes
// exactly +0.0f (inputs are guarded gmem zeros or out-of-range zeros of the
// previous level), so only global stores need predicates.

#define TPB 256
#define TT  64   // level-6 outputs per block

#define RL0  0.23037781330885523f
#define RL1  0.7148465705525415f
#define RL2  0.6308807679295904f
#define RL3 -0.02798376941698385f
#define RL4 -0.18703481171888114f
#define RL5  0.030841381835986965f
#define RL6  0.032883011666982945f
#define RL7 -0.010597401784997278f
#define RH0 -0.010597401784997278f
#define RH1 -0.032883011666982945f
#define RH2  0.030841381835986965f
#define RH3  0.18703481171888114f
#define RH4 -0.02798376941698385f
#define RH5 -0.6308807679295904f
#define RH6  0.7148465705525415f
#define RH7 -0.23037781330885523f

// Same accumulation order everywhere -> bit-identical across rounds.
__device__ __forceinline__ void conv8(const float* v, float& lo, float& hi) {
    float l = 0.f, h = 0.f;
    l = fmaf(v[0], RL0, l);  h = fmaf(v[0], RH0, h);
    l = fmaf(v[1], RL1, l);  h = fmaf(v[1], RH1, h);
    l = fmaf(v[2], RL2, l);  h = fmaf(v[2], RH2, h);
    l = fmaf(v[3], RL3, l);  h = fmaf(v[3], RH3, h);
    l = fmaf(v[4], RL4, l);  h = fmaf(v[4], RH4, h);
    l = fmaf(v[5], RL5, l);  h = fmaf(v[5], RH5, h);
    l = fmaf(v[6], RL6, l);  h = fmaf(v[6], RH6, h);
    l = fmaf(v[7], RL7, l);  h = fmaf(v[7], RH7, h);
    lo = l; hi = h;
}

__device__ __forceinline__ float ldx(const float* __restrict__ xr, int idx) {
    return ((unsigned)idx < 262144u) ? __ldg(xr + idx) : 0.f;
}

// Output element-offset layout (row-major [64, M] each):
//   a:0(4102)  d6:262528(4102)  d5:525056(8198)  d4:1049728(16390)
//   d3:2098688(32774)  d2:4196224(65541)  d1:8390848(131075)

// Levels 2-6: input cA from smem.
template<int P, int LEN, int H, int DBASE, bool LAST>
__device__ __forceinline__ void level_shfl(const float* __restrict__ sin,
                                           float* __restrict__ sout,
                                           float* __restrict__ out,
                                           int c, int r, int tid) {
    constexpr int S     = TT * P + H;                 // outputs (even)
    constexpr int NP    = S / 2;                      // pairs
    constexpr int NPPAD = ((NP + 31) / 32) * 32;      // warp-padded
    const int base = c * (TT * P) - H;
    float* __restrict__ dr = out + (size_t)DBASE + (size_t)r * LEN;
    float* __restrict__ ar = out + (size_t)r * LEN;   // only when LAST
    const int lane = tid & 31;
    // float2-store alignment of (DBASE + r*LEN + even): uniform per block.
    const bool al2 = ((((unsigned)DBASE + (unsigned)r * (unsigned)LEN) & 1u) == 0u);

    for (int jp = tid; jp < NPPAD; jp += TPB) {
        // own 4 dense floats: sin[4jp .. 4jp+3] (16B-aligned, dense per warp)
        const float4 a4 = *(const float4*)(sin + 4 * jp);
        float v[10];
        v[0] = a4.x; v[1] = a4.y; v[2] = a4.z; v[3] = a4.w;
        v[4] = __shfl_down_sync(0xffffffffu, a4.x, 1);
        v[5] = __shfl_down_sync(0xffffffffu, a4.y, 1);
        v[6] = __shfl_down_sync(0xffffffffu, a4.z, 1);
        v[7] = __shfl_down_sync(0xffffffffu, a4.w, 1);
        v[8] = __shfl_down_sync(0xffffffffu, a4.x, 2);
        v[9] = __shfl_down_sync(0xffffffffu, a4.y, 2);
        if (lane == 31) {                  // +1 neighbor is next warp
            const float4 nb = *(const float4*)(sin + 4 * jp + 4);
            v[4] = nb.x; v[5] = nb.y; v[6] = nb.z; v[7] = nb.w;
        }
        if (lane >= 30) {                  // +2 neighbor crosses warp
            const float2 nc = *(const float2*)(sin + 4 * jp + 8);
            v[8] = nc.x; v[9] = nc.y;
        }
        float lo0, hi0, lo1, hi1;
        conv8(v,     lo0, hi0);
        conv8(v + 2, lo1, hi1);

        if (jp < NP) {
            const int j0 = 2 * jp;
            if (!LAST) *(float2*)(sout + j0) = make_float2(lo0, lo1);
            const int g0 = base + j0;
            if (j0 >= H) {                            // g0 >= 0 here
                if (al2 && (unsigned)(g0 + 1) < (unsigned)LEN) {
                    *(float2*)(dr + g0) = make_float2(hi0, hi1);
                    if (LAST) *(float2*)(ar + g0) = make_float2(lo0, lo1);
                } else {
                    if ((unsigned)g0 < (unsigned)LEN) {
                        dr[g0] = hi0;  if (LAST) ar[g0] = lo0;
                    }
                    if ((unsigned)(g0 + 1) < (unsigned)LEN) {
                        dr[g0 + 1] = hi1;  if (LAST) ar[g0 + 1] = lo1;
                    }
                }
            }
        }
    }
}

__global__ void __launch_bounds__(TPB)
dwt6_fused_kernel(const float* __restrict__ x, float* __restrict__ out) {
    // Sized for padded-loop overreach of their CONSUMER level:
    // need >= 4*(NPPAD_consumer-1)+10 floats.
    __shared__ __align__(16) float s1[2312];  // valid 2234; L2 NPPAD=576
    __shared__ __align__(16) float s2[1160];  // valid 1114; L3 NPPAD=288
    __shared__ __align__(16) float s3[648];   // valid  554; L4 NPPAD=160
    __shared__ __align__(16) float s4[392];   // valid  274; L5 NPPAD=96
    __shared__ __align__(16) float s5[136];   // valid  134; L6 NPPAD=32

    const int c   = blockIdx.x;
    const int r   = blockIdx.y;
    const int tid = threadIdx.x;
    const int lane = tid & 31;
    const float* __restrict__ xr = x + (size_t)r * 262144;

    // ---- Level 1: gmem -> (s1, d1) ----
    {
        constexpr int LEN = 131075, H = 186, NP = 1117, NPPAD = 1120;
        const int base = c * 2048 - H;                 // even
        float* __restrict__ dr = out + (size_t)8390848 + (size_t)r * LEN;
        const bool al2 = ((r & 1) == 0);               // 8390848 even, LEN odd

        for (int jp = tid; jp < NPPAD; jp += TPB) {
            const int g0 = base + 2 * jp;              // even
            const int t0 = 2 * g0 - 4;                 // 16B-aligned
            float4 own;
            if ((unsigned)t0 < 262141u) {              // t0>=0 && t0+3<262144
                own = *(const float4*)(xr + t0);
            } else {
                own.x = ldx(xr, t0);     own.y = ldx(xr, t0 + 1);
                own.z = ldx(xr, t0 + 2); own.w = ldx(xr, t0 + 3);
            }
            float v[10];
            v[2] = own.x; v[3] = own.y; v[4] = own.z; v[5] = own.w;
            v[0] = __shfl_up_sync  (0xffffffffu, own.z, 1);  // x[2g0-6]
            v[1] = __shfl_up_sync  (0xffffffffu, own.w, 1);  // x[2g0-5]
            v[6] = __shfl_down_sync(0xffffffffu, own.x, 1);  // x[2g0]
            v[7] = __shfl_down_sync(0xffffffffu, own.y, 1);
            v[8] = __shfl_down_sync(0xffffffffu, own.z, 1);
            v[9] = __shfl_down_sync(0xffffffffu, own.w, 1);
            if (lane == 0) {
                v[0] = ldx(xr, 2 * g0 - 6);
                v[1] = ldx(xr, 2 * g0 - 5);
            }
            if (lane == 31) {
                v[6] = ldx(xr, 2 * g0);     v[7] = ldx(xr, 2 * g0 + 1);
                v[8] = ldx(xr, 2 * g0 + 2); v[9] = ldx(xr, 2 * g0 + 3);
            }
            float lo0, hi0, lo1, hi1;
            conv8(v,     lo0, hi0);
            conv8(v + 2, lo1, hi1);

            if (jp < NP) {
                const int j0 = 2 * jp;
                *(float2*)(s1 + j0) = make_float2(lo0, lo1);
                if (j0 >= H) {                         // g0 >= 0 here
                    if (al2 && (unsigned)(g0 + 1) < (unsigned)LEN) {
                        *(float2*)(dr + g0) = make_float2(hi0, hi1);
                    } else {
                        if ((unsigned)g0       < (unsigned)LEN) dr[g0]     = hi0;
                        if ((unsigned)(g0 + 1) < (unsigned)LEN) dr[g0 + 1] = hi1;
                    }
                }
            }
        }
    }
    __syncthreads();

    level_shfl<16, 65541, 90, 4196224, false>(s1, s2, out, c, r, tid);  // d2
    __syncthreads();
    level_shfl< 8, 32774, 42, 2098688, false>(s2, s3, out, c, r, tid);  // d3
    __syncthreads();
    level_shfl< 4, 16390, 18, 1049728, false>(s3, s4, out, c, r, tid);  // d4
    __syncthreads();
    level_shfl< 2,  8198,  6,  525056, false>(s4, s5, out, c, r, tid);  // d5
    __syncthreads();
    level_shfl< 1,  4102,  0,  262528, true >(s5, (float*)0, out, c, r, tid);  // d6 + a
}

extern "C" void kernel_launch(void* const* d_in, const int* in_sizes, int n_in,
                              void* d_out, int out_size) {
    const float* x = (const float*)d_in[0];
    float* out = (float*)d_out;
    const int rows = in_sizes[0] / 262144;          // 64
    const int chunks = (4102 + TT - 1) / TT;        // 65
    dim3 grid(chunks, rows);
    dwt6_fused_kernel<<<grid, TPB>>>(x, out);
}

// round 15
// speedup vs baseline: 1.1730x; 1.1730x over previous
#include <cuda_runtime.h>
#include <cuda_bf16.h>

// 6-level cascaded db4 DWT, zero-padding, fully fused.
// Level 1: pair-per-thread directly from gmem (R13 scheme), writing its cA
// into PARITY-SPLIT smem arrays (e[i]=cA[2i], o[i]=cA[2i+1]).
// Levels 2-6: QUAD-per-thread consumers; outputs j0..j0+3 need only
// e[j0..j0+6], o[j0..j0+6] -> 4 conflict-free LDS.128 (16B lane stride),
// no redundant middle loads. FMA tap order identical to reference.
//
// Zero-pad invariant: slots with global index outside [0,LEN) compute exactly
// +0.0f (guarded gmem loads at level 1; induction through e/o arrays).
// Padded-quad slots (local j >= S) may hold garbage but are provably never
// read by any valid output and never stored (store predicate includes j<S).

#define TPB 256
#define TT  64   // level-6 outputs per block

#define RL0  0.23037781330885523f
#define RL1  0.7148465705525415f
#define RL2  0.6308807679295904f
#define RL3 -0.02798376941698385f
#define RL4 -0.18703481171888114f
#define RL5  0.030841381835986965f
#define RL6  0.032883011666982945f
#define RL7 -0.010597401784997278f
#define RH0 -0.010597401784997278f
#define RH1 -0.032883011666982945f
#define RH2  0.030841381835986965f
#define RH3  0.18703481171888114f
#define RH4 -0.02798376941698385f
#define RH5 -0.6308807679295904f
#define RH6  0.7148465705525415f
#define RH7 -0.23037781330885523f

// Same accumulation order as all prior rounds -> bit-identical.
__device__ __forceinline__ void conv8(const float* v, float& lo, float& hi) {
    float l = 0.f, h = 0.f;
    l = fmaf(v[0], RL0, l);  h = fmaf(v[0], RH0, h);
    l = fmaf(v[1], RL1, l);  h = fmaf(v[1], RH1, h);
    l = fmaf(v[2], RL2, l);  h = fmaf(v[2], RH2, h);
    l = fmaf(v[3], RL3, l);  h = fmaf(v[3], RH3, h);
    l = fmaf(v[4], RL4, l);  h = fmaf(v[4], RH4, h);
    l = fmaf(v[5], RL5, l);  h = fmaf(v[5], RH5, h);
    l = fmaf(v[6], RL6, l);  h = fmaf(v[6], RH6, h);
    l = fmaf(v[7], RL7, l);  h = fmaf(v[7], RH7, h);
    lo = l; hi = h;
}

// Parity-sourced variant, identical FMA sequence (e[k]=v[2k], o[k]=v[2k+1]).
__device__ __forceinline__ void conv8eo(const float* e, const float* o,
                                        float& lo, float& hi) {
    float l = 0.f, h = 0.f;
    l = fmaf(e[0], RL0, l);  h = fmaf(e[0], RH0, h);
    l = fmaf(o[0], RL1, l);  h = fmaf(o[0], RH1, h);
    l = fmaf(e[1], RL2, l);  h = fmaf(e[1], RH2, h);
    l = fmaf(o[1], RL3, l);  h = fmaf(o[1], RH3, h);
    l = fmaf(e[2], RL4, l);  h = fmaf(e[2], RH4, h);
    l = fmaf(o[2], RL5, l);  h = fmaf(o[2], RH5, h);
    l = fmaf(e[3], RL6, l);  h = fmaf(e[3], RH6, h);
    l = fmaf(o[3], RL7, l);  h = fmaf(o[3], RH7, h);
    lo = l; hi = h;
}

__device__ __forceinline__ float ldx(const float* __restrict__ xr, int idx) {
    return ((unsigned)idx < 262144u) ? __ldg(xr + idx) : 0.f;
}

// Output element-offset layout (row-major [64, M] each):
//   a:0(4102)  d6:262528(4102)  d5:525056(8198)  d4:1049728(16390)
//   d3:2098688(32774)  d2:4196224(65541)  d1:8390848(131075)

// Levels 2-6: parity-split smem in, parity-split smem out (unless LAST).
template<int P, int LEN, int H, int DBASE, bool LAST>
__device__ __forceinline__ void level_quad(const float* __restrict__ ein,
                                           const float* __restrict__ oin,
                                           float* __restrict__ eout,
                                           float* __restrict__ oout,
                                           float* __restrict__ out,
                                           int c, int r, int tid) {
    constexpr int S  = TT * P + H;        // outputs at this level
    constexpr int NQ = (S + 3) / 4;       // quads (may overhang S)
    const int base = c * (TT * P) - H;
    float* __restrict__ dr = out + (size_t)DBASE + (size_t)r * LEN;
    float* __restrict__ ar = out + (size_t)r * LEN;  // only when LAST
    const bool al2 = ((((unsigned)DBASE + (unsigned)r * (unsigned)LEN) & 1u) == 0u);

    for (int q = tid; q < NQ; q += TPB) {
        const int j0 = 4 * q;
        // e/o windows e[j0..j0+6], o[j0..j0+6]: 4 conflict-free LDS.128
        const float4 ea = *(const float4*)(ein + j0);
        const float4 oa = *(const float4*)(oin + j0);
        const float4 eb = *(const float4*)(ein + j0 + 4);
        const float4 ob = *(const float4*)(oin + j0 + 4);
        const float ev[7] = { ea.x, ea.y, ea.z, ea.w, eb.x, eb.y, eb.z };
        const float ov[7] = { oa.x, oa.y, oa.z, oa.w, ob.x, ob.y, ob.z };
        float lo[4], hi[4];
        #pragma unroll
        for (int i = 0; i < 4; i++) conv8eo(ev + i, ov + i, lo[i], hi[i]);

        if (!LAST) {   // parity-split: slot j0+2k -> eout[2q+k], j0+2k+1 -> oout[2q+k]
            *(float2*)(eout + 2 * q) = make_float2(lo[0], lo[2]);
            *(float2*)(oout + 2 * q) = make_float2(lo[1], lo[3]);
        }
        const int g0 = base + j0;
        // j0 >= H: since H % 4 == 2 (or 0) and j0 % 4 == 0, j0 >= H implies
        // all four slots >= H. Fast path needs full quad valid + in-range.
        if (j0 >= H && j0 + 4 <= S && g0 + 4 <= LEN && al2) {
            *(float2*)(dr + g0)     = make_float2(hi[0], hi[1]);
            *(float2*)(dr + g0 + 2) = make_float2(hi[2], hi[3]);
            if (LAST) {
                *(float2*)(ar + g0)     = make_float2(lo[0], lo[1]);
                *(float2*)(ar + g0 + 2) = make_float2(lo[2], lo[3]);
            }
        } else {
            #pragma unroll
            for (int i = 0; i < 4; i++) {
                const int j = j0 + i;
                if (j >= H && j < S && (unsigned)(g0 + i) < (unsigned)LEN) {
                    dr[g0 + i] = hi[i];
                    if (LAST) ar[g0 + i] = lo[i];
                }
            }
        }
    }
}

__global__ void __launch_bounds__(TPB)
dwt6_fused_kernel(const float* __restrict__ x, float* __restrict__ out) {
    // Parity arrays; sized for consumer f4 overreach (max idx 4*(NQ-1)+7).
    __shared__ __align__(16) float e1[1120], o1[1120];  // valid 1117; L2 NQ=279
    __shared__ __align__(16) float e2[560],  o2[560];   // valid 557;  L3 NQ=139
    __shared__ __align__(16) float e3[280],  o3[280];   // valid 277;  L4 NQ=69
    __shared__ __align__(16) float e4[140],  o4[140];   // valid 137;  L5 NQ=34
    __shared__ __align__(16) float e5[68],   o5[68];    // valid 67;   L6 NQ=16

    const int c   = blockIdx.x;
    const int r   = blockIdx.y;
    const int tid = threadIdx.x;
    const float* __restrict__ xr = x + (size_t)r * 262144;

    // ---- Level 1: gmem -> (e1/o1, d1), pair per thread (R13 scheme) ----
    {
        constexpr int LEN = 131075, H = 186, NP = 1117;   // S1 = 2234
        const int base = c * 2048 - H;                    // even
        float* __restrict__ dr = out + (size_t)8390848 + (size_t)r * LEN;
        const bool al2 = ((r & 1) == 0);                  // LEN odd

        for (int jp = tid; jp < NP; jp += TPB) {
            const int j0 = 2 * jp;
            const int g0 = base + j0;                     // even
            float lo0, hi0, lo1, hi1;
            // window x[2g0-6 .. 2g0+3]
            if ((unsigned)(g0 - 3) <= 131067u) {          // fully in-bounds
                const float2 a2 = *(const float2*)(xr + 2 * g0 - 6);
                const float4 b4 = *(const float4*)(xr + 2 * g0 - 4);
                const float4 c4 = *(const float4*)(xr + 2 * g0);
                const float v[10] = { a2.x, a2.y, b4.x, b4.y, b4.z, b4.w,
                                      c4.x, c4.y, c4.z, c4.w };
                conv8(v,     lo0, hi0);
                conv8(v + 2, lo1, hi1);
            } else {
                float v[10];
                #pragma unroll
                for (int m = 0; m < 10; m++) v[m] = ldx(xr, 2 * g0 - 6 + m);
                conv8(v,     lo0, hi0);
                conv8(v + 2, lo1, hi1);
            }
            e1[jp] = lo0;   // dense scalar stores (1 wavefront each)
            o1[jp] = lo1;
            if (j0 >= H) {
                if (al2 && (unsigned)(g0 + 1) < (unsigned)LEN) {
                    *(float2*)(dr + g0) = make_float2(hi0, hi1);
                } else {
                    if ((unsigned)g0       < (unsigned)LEN) dr[g0]     = hi0;
                    if ((unsigned)(g0 + 1) < (unsigned)LEN) dr[g0 + 1] = hi1;
                }
            }
        }
    }
    __syncthreads();

    level_quad<16, 65541, 90, 4196224, false>(e1, o1, e2, o2, out, c, r, tid);  // d2
    __syncthreads();
    level_quad< 8, 32774, 42, 2098688, false>(e2, o2, e3, o3, out, c, r, tid);  // d3
    __syncthreads();
    level_quad< 4, 16390, 18, 1049728, false>(e3, o3, e4, o4, out, c, r, tid);  // d4
    __syncthreads();
    level_quad< 2,  8198,  6,  525056, false>(e4, o4, e5, o5, out, c, r, tid);  // d5
    __syncthreads();
    level_quad< 1,  4102,  0,  262528, true >(e5, o5, (float*)0, (float*)0,
                                              out, c, r, tid);                   // d6 + a
}

extern "C" void kernel_launch(void* const* d_in, const int* in_sizes, int n_in,
                              void* d_out, int out_size) {
    const float* x = (const float*)d_in[0];
    float* out = (float*)d_out;
    const int rows = in_sizes[0] / 262144;          // 64
    const int chunks = (4102 + TT - 1) / TT;        // 65
    dim3 grid(chunks, rows);
    dwt6_fused_kernel<<<grid, TPB>>>(x, out);
}

// round 16
// speedup vs baseline: 1.1881x; 1.0128x over previous
#include <cuda_runtime.h>
#include <cuda_bf16.h>

// 6-level cascaded db4 DWT, zero-padding, fully fused (R13 structure).
// Level 1: QUAD-per-thread from gmem — 16-float aligned window
// (f2@2g0-6, f4@2g0-4, f4@2g0, f4@2g0+4, f2@2g0+8), 4 outputs/iter,
// NQ=559 (2.2 iters/thread keeps gmem MLP). s1 written as aligned float4.
// Levels 2-6: pair-per-thread from smem (f4+f4+f2 window) — the proven
// R13 scheme (iteration counts >= 1 for all threads, best latency hiding).
//
// Zero-pad invariant: slots with global index outside [0,LEN) compute
// exactly +0.0f (guarded gmem loads at level 1; induction upward), so only
// global stores are predicated. Level-1 quad overhang slots (j=2234,2235)
// are never read (L2 max read index 2233) and never stored (j<S predicate).

#define TPB 256
#define TT  64   // level-6 outputs per block

#define RL0  0.23037781330885523f
#define RL1  0.7148465705525415f
#define RL2  0.6308807679295904f
#define RL3 -0.02798376941698385f
#define RL4 -0.18703481171888114f
#define RL5  0.030841381835986965f
#define RL6  0.032883011666982945f
#define RL7 -0.010597401784997278f
#define RH0 -0.010597401784997278f
#define RH1 -0.032883011666982945f
#define RH2  0.030841381835986965f
#define RH3  0.18703481171888114f
#define RH4 -0.02798376941698385f
#define RH5 -0.6308807679295904f
#define RH6  0.7148465705525415f
#define RH7 -0.23037781330885523f

// Same accumulation order as all prior rounds -> bit-identical.
__device__ __forceinline__ void conv8(const float* v, float& lo, float& hi) {
    float l = 0.f, h = 0.f;
    l = fmaf(v[0], RL0, l);  h = fmaf(v[0], RH0, h);
    l = fmaf(v[1], RL1, l);  h = fmaf(v[1], RH1, h);
    l = fmaf(v[2], RL2, l);  h = fmaf(v[2], RH2, h);
    l = fmaf(v[3], RL3, l);  h = fmaf(v[3], RH3, h);
    l = fmaf(v[4], RL4, l);  h = fmaf(v[4], RH4, h);
    l = fmaf(v[5], RL5, l);  h = fmaf(v[5], RH5, h);
    l = fmaf(v[6], RL6, l);  h = fmaf(v[6], RH6, h);
    l = fmaf(v[7], RL7, l);  h = fmaf(v[7], RH7, h);
    lo = l; hi = h;
}

__device__ __forceinline__ float ldx(const float* __restrict__ xr, int idx) {
    return ((unsigned)idx < 262144u) ? __ldg(xr + idx) : 0.f;
}

// Output element-offset layout (row-major [64, M] each):
//   a:0(4102)  d6:262528(4102)  d5:525056(8198)  d4:1049728(16390)
//   d3:2098688(32774)  d2:4196224(65541)  d1:8390848(131075)

// Levels 2-6: pair-per-thread from smem (R13 scheme, verbatim).
template<int P, int LEN, int H, int DBASE, bool LAST>
__device__ __forceinline__ void level_pair(const float* __restrict__ sin,
                                           float* __restrict__ sout,
                                           float* __restrict__ out,
                                           int c, int r, int tid) {
    constexpr int S  = TT * P + H;   // outputs at this level (even)
    constexpr int NP = S / 2;
    const int base = c * (TT * P) - H;
    float* __restrict__ dr = out + (size_t)DBASE + (size_t)r * LEN;
    float* __restrict__ ar = out + (size_t)r * LEN;   // only when LAST
    const bool al2 = ((((unsigned)DBASE + (unsigned)r * (unsigned)LEN) & 1u) == 0u);

    for (int jp = tid; jp < NP; jp += TPB) {
        const int j0 = 2 * jp;
        const float4 a4 = *(const float4*)(sin + 2 * j0);
        const float4 b4 = *(const float4*)(sin + 2 * j0 + 4);
        const float2 c2 = *(const float2*)(sin + 2 * j0 + 8);
        const float v[10] = { a4.x, a4.y, a4.z, a4.w,
                              b4.x, b4.y, b4.z, b4.w, c2.x, c2.y };
        float lo0, hi0, lo1, hi1;
        conv8(v,     lo0, hi0);
        conv8(v + 2, lo1, hi1);

        if (!LAST) *(float2*)(sout + j0) = make_float2(lo0, lo1);

        const int g0 = base + j0;
        if (j0 >= H) {
            if (al2 && (unsigned)(g0 + 1) < (unsigned)LEN) {
                *(float2*)(dr + g0) = make_float2(hi0, hi1);
                if (LAST) *(float2*)(ar + g0) = make_float2(lo0, lo1);
            } else {
                if ((unsigned)g0 < (unsigned)LEN) {
                    dr[g0] = hi0;  if (LAST) ar[g0] = lo0;
                }
                if ((unsigned)(g0 + 1) < (unsigned)LEN) {
                    dr[g0 + 1] = hi1;  if (LAST) ar[g0 + 1] = lo1;
                }
            }
        }
    }
}

__global__ void __launch_bounds__(TPB)
dwt6_fused_kernel(const float* __restrict__ x, float* __restrict__ out) {
    __shared__ __align__(16) float s1[2240];  // valid 2236 (2234 + overhang 2)
    __shared__ __align__(16) float s2[1120];  // valid 1114
    __shared__ __align__(16) float s3[560];   // valid  554
    __shared__ __align__(16) float s4[288];   // valid  274
    __shared__ __align__(16) float s5[144];   // valid  134

    const int c   = blockIdx.x;
    const int r   = blockIdx.y;
    const int tid = threadIdx.x;
    const float* __restrict__ xr = x + (size_t)r * 262144;

    // ---- Level 1: gmem -> (s1, d1), QUAD per thread ----
    {
        constexpr int LEN = 131075, H = 186, S = 2234;
        constexpr int NQ = (S + 3) / 4;                // 559
        const int base = c * 2048 - H;                 // == 2 (mod 4)
        float* __restrict__ dr = out + (size_t)8390848 + (size_t)r * LEN;
        const bool al2 = ((r & 1) == 0);               // LEN odd

        for (int q = tid; q < NQ; q += TPB) {
            const int j0 = 4 * q;
            const int g0 = base + j0;                  // even
            const int t0 = 2 * g0 - 6;                 // window start
            float v[16];                               // x[t0 .. t0+15]
            if ((unsigned)t0 <= 262128u) {             // t0>=0 && t0+15<262144
                const float2 a2 = *(const float2*)(xr + t0);
                const float4 b4 = *(const float4*)(xr + t0 + 2);
                const float4 c4 = *(const float4*)(xr + t0 + 6);
                const float4 d4 = *(const float4*)(xr + t0 + 10);
                const float2 e2 = *(const float2*)(xr + t0 + 14);
                v[0]=a2.x;  v[1]=a2.y;
                v[2]=b4.x;  v[3]=b4.y;  v[4]=b4.z;  v[5]=b4.w;
                v[6]=c4.x;  v[7]=c4.y;  v[8]=c4.z;  v[9]=c4.w;
                v[10]=d4.x; v[11]=d4.y; v[12]=d4.z; v[13]=d4.w;
                v[14]=e2.x; v[15]=e2.y;
            } else {
                #pragma unroll
                for (int m = 0; m < 16; m++) v[m] = ldx(xr, t0 + m);
            }
            float lo[4], hi[4];
            #pragma unroll
            for (int i = 0; i < 4; i++) conv8(v + 2 * i, lo[i], hi[i]);

            *(float4*)(s1 + j0) = make_float4(lo[0], lo[1], lo[2], lo[3]);

            if (j0 >= H && j0 + 4 <= S && g0 + 4 <= LEN && al2) {
                *(float2*)(dr + g0)     = make_float2(hi[0], hi[1]);
                *(float2*)(dr + g0 + 2) = make_float2(hi[2], hi[3]);
            } else {
                #pragma unroll
                for (int i = 0; i < 4; i++) {
                    const int j = j0 + i;
                    if (j >= H && j < S && (unsigned)(g0 + i) < (unsigned)LEN)
                        dr[g0 + i] = hi[i];
                }
            }
        }
    }
    __syncthreads();

    level_pair<16, 65541, 90, 4196224, false>(s1, s2, out, c, r, tid);  // d2
    __syncthreads();
    level_pair< 8, 32774, 42, 2098688, false>(s2, s3, out, c, r, tid);  // d3
    __syncthreads();
    level_pair< 4, 16390, 18, 1049728, false>(s3, s4, out, c, r, tid);  // d4
    __syncthreads();
    level_pair< 2,  8198,  6,  525056, false>(s4, s5, out, c, r, tid);  // d5
    __syncthreads();
    level_pair< 1,  4102,  0,  262528, true >(s5, (float*)0, out, c, r, tid);  // d6 + a
}

extern "C" void kernel_launch(void* const* d_in, const int* in_sizes, int n_in,
                              void* d_out, int out_size) {
    const float* x = (const float*)d_in[0];
    float* out = (float*)d_out;
    const int rows = in_sizes[0] / 262144;          // 64
    const int chunks = (4102 + TT - 1) / TT;        // 65
    dim3 grid(chunks, rows);
    dwt6_fused_kernel<<<grid, TPB>>>(x, out);
}

// round 17
// speedup vs baseline: 1.2369x; 1.0411x over previous
#include <cuda_runtime.h>
#include <cuda_bf16.h>

// 6-level cascaded db4 DWT, zero-padding, fully fused.
// R13 structure (pair-per-thread everywhere, gmem level 1) with PARITY-SPLIT
// smem cA buffers: e[i]=cA[2i], o[i]=cA[2i+1]. A consumer pair (j0=2jp,j0+1)
// reads e[2jp..2jp+4], o[2jp..2jp+4] -> lane stride 8B: dense f2 loads
// (2 wavefronts) instead of 32B-stride f4 (8 wavefronts). Producers write
// dense scalars e[jp], o[jp]. Iteration counts identical to R13.
//
// Exact-fit algebra: S_in = 2*S + 6, so each e/o array has S+3 entries =
// NP of its producer; consumer max read index 2(NP-1)+4 = S+2 = size-1.
//
// Zero-pad invariant: slots with global index outside [0,LEN) compute exactly
// +0.0f (guarded gmem loads at level 1; induction upward), so only global
// stores are predicated. FMA tap order identical to reference in all paths.

#define TPB 256
#define TT  64   // level-6 outputs per block

#define RL0  0.23037781330885523f
#define RL1  0.7148465705525415f
#define RL2  0.6308807679295904f
#define RL3 -0.02798376941698385f
#define RL4 -0.18703481171888114f
#define RL5  0.030841381835986965f
#define RL6  0.032883011666982945f
#define RL7 -0.010597401784997278f
#define RH0 -0.010597401784997278f
#define RH1 -0.032883011666982945f
#define RH2  0.030841381835986965f
#define RH3  0.18703481171888114f
#define RH4 -0.02798376941698385f
#define RH5 -0.6308807679295904f
#define RH6  0.7148465705525415f
#define RH7 -0.23037781330885523f

// Same accumulation order as all prior rounds -> bit-identical.
__device__ __forceinline__ void conv8(const float* v, float& lo, float& hi) {
    float l = 0.f, h = 0.f;
    l = fmaf(v[0], RL0, l);  h = fmaf(v[0], RH0, h);
    l = fmaf(v[1], RL1, l);  h = fmaf(v[1], RH1, h);
    l = fmaf(v[2], RL2, l);  h = fmaf(v[2], RH2, h);
    l = fmaf(v[3], RL3, l);  h = fmaf(v[3], RH3, h);
    l = fmaf(v[4], RL4, l);  h = fmaf(v[4], RH4, h);
    l = fmaf(v[5], RL5, l);  h = fmaf(v[5], RH5, h);
    l = fmaf(v[6], RL6, l);  h = fmaf(v[6], RH6, h);
    l = fmaf(v[7], RL7, l);  h = fmaf(v[7], RH7, h);
    lo = l; hi = h;
}

// Parity-sourced, identical FMA sequence (e[k]=v[2k], o[k]=v[2k+1]).
__device__ __forceinline__ void conv8eo(const float* e, const float* o,
                                        float& lo, float& hi) {
    float l = 0.f, h = 0.f;
    l = fmaf(e[0], RL0, l);  h = fmaf(e[0], RH0, h);
    l = fmaf(o[0], RL1, l);  h = fmaf(o[0], RH1, h);
    l = fmaf(e[1], RL2, l);  h = fmaf(e[1], RH2, h);
    l = fmaf(o[1], RL3, l);  h = fmaf(o[1], RH3, h);
    l = fmaf(e[2], RL4, l);  h = fmaf(e[2], RH4, h);
    l = fmaf(o[2], RL5, l);  h = fmaf(o[2], RH5, h);
    l = fmaf(e[3], RL6, l);  h = fmaf(e[3], RH6, h);
    l = fmaf(o[3], RL7, l);  h = fmaf(o[3], RH7, h);
    lo = l; hi = h;
}

__device__ __forceinline__ float ldx(const float* __restrict__ xr, int idx) {
    return ((unsigned)idx < 262144u) ? __ldg(xr + idx) : 0.f;
}

// Output element-offset layout (row-major [64, M] each):
//   a:0(4102)  d6:262528(4102)  d5:525056(8198)  d4:1049728(16390)
//   d3:2098688(32774)  d2:4196224(65541)  d1:8390848(131075)

// Levels 2-6: pair-per-thread, parity-split in/out.
template<int P, int LEN, int H, int DBASE, bool LAST>
__device__ __forceinline__ void level_pair_eo(const float* __restrict__ ein,
                                              const float* __restrict__ oin,
                                              float* __restrict__ eout,
                                              float* __restrict__ oout,
                                              float* __restrict__ out,
                                              int c, int r, int tid) {
    constexpr int S  = TT * P + H;   // outputs at this level (even)
    constexpr int NP = S / 2;
    const int base = c * (TT * P) - H;
    float* __restrict__ dr = out + (size_t)DBASE + (size_t)r * LEN;
    float* __restrict__ ar = out + (size_t)r * LEN;   // only when LAST
    const bool al2 = ((((unsigned)DBASE + (unsigned)r * (unsigned)LEN) & 1u) == 0u);

    for (int jp = tid; jp < NP; jp += TPB) {
        const int i0 = 2 * jp;                // even -> 8B-aligned f2 loads
        // windows e[i0..i0+4], o[i0..i0+4]: dense f2+f2+scalar each
        const float2 e01 = *(const float2*)(ein + i0);
        const float2 e23 = *(const float2*)(ein + i0 + 2);
        const float  e4  = ein[i0 + 4];
        const float2 o01 = *(const float2*)(oin + i0);
        const float2 o23 = *(const float2*)(oin + i0 + 2);
        const float  o4  = oin[i0 + 4];
        const float ev[5] = { e01.x, e01.y, e23.x, e23.y, e4 };
        const float ov[5] = { o01.x, o01.y, o23.x, o23.y, o4 };
        float lo0, hi0, lo1, hi1;
        conv8eo(ev,     ov,     lo0, hi0);    // output j0 = 2*jp
        conv8eo(ev + 1, ov + 1, lo1, hi1);    // output j0+1

        if (!LAST) {
            eout[jp] = lo0;                   // dense scalar stores
            oout[jp] = lo1;
        }
        const int j0 = 2 * jp;
        const int g0 = base + j0;
        if (j0 >= H) {
            if (al2 && (unsigned)(g0 + 1) < (unsigned)LEN) {
                *(float2*)(dr + g0) = make_float2(hi0, hi1);
                if (LAST) *(float2*)(ar + g0) = make_float2(lo0, lo1);
            } else {
                if ((unsigned)g0 < (unsigned)LEN) {
                    dr[g0] = hi0;  if (LAST) ar[g0] = lo0;
                }
                if ((unsigned)(g0 + 1) < (unsigned)LEN) {
                    dr[g0 + 1] = hi1;  if (LAST) ar[g0 + 1] = lo1;
                }
            }
        }
    }
}

__global__ void __launch_bounds__(TPB)
dwt6_fused_kernel(const float* __restrict__ x, float* __restrict__ out) {
    // Parity arrays; consumer of level l needs S_l+3 entries (exact fit):
    __shared__ __align__(16) float e1[1120], o1[1120];  // valid 1117
    __shared__ __align__(16) float e2[560],  o2[560];   // valid 557
    __shared__ __align__(16) float e3[280],  o3[280];   // valid 277
    __shared__ __align__(16) float e4[140],  o4[140];   // valid 137
    __shared__ __align__(16) float e5[68],   o5[68];    // valid 67

    const int c   = blockIdx.x;
    const int r   = blockIdx.y;
    const int tid = threadIdx.x;
    const float* __restrict__ xr = x + (size_t)r * 262144;

    // ---- Level 1: gmem -> (e1/o1, d1), pair per thread (R13 scheme) ----
    {
        constexpr int LEN = 131075, H = 186, NP = 1117;   // S1 = 2234
        const int base = c * 2048 - H;                    // even
        float* __restrict__ dr = out + (size_t)8390848 + (size_t)r * LEN;
        const bool al2 = ((r & 1) == 0);                  // LEN odd

        for (int jp = tid; jp < NP; jp += TPB) {
            const int j0 = 2 * jp;
            const int g0 = base + j0;                     // even
            float lo0, hi0, lo1, hi1;
            // window x[2g0-6 .. 2g0+3]
            if ((unsigned)(g0 - 3) <= 131067u) {          // fully in-bounds
                const float2 a2 = *(const float2*)(xr + 2 * g0 - 6);
                const float4 b4 = *(const float4*)(xr + 2 * g0 - 4);
                const float4 c4 = *(const float4*)(xr + 2 * g0);
                const float v[10] = { a2.x, a2.y, b4.x, b4.y, b4.z, b4.w,
                                      c4.x, c4.y, c4.z, c4.w };
                conv8(v,     lo0, hi0);
                conv8(v + 2, lo1, hi1);
            } else {
                float v[10];
                #pragma unroll
                for (int m = 0; m < 10; m++) v[m] = ldx(xr, 2 * g0 - 6 + m);
                conv8(v,     lo0, hi0);
                conv8(v + 2, lo1, hi1);
            }
            e1[jp] = lo0;                                 // dense scalar stores
            o1[jp] = lo1;
            if (j0 >= H) {
                if (al2 && (unsigned)(g0 + 1) < (unsigned)LEN) {
                    *(float2*)(dr + g0) = make_float2(hi0, hi1);
                } else {
                    if ((unsigned)g0       < (unsigned)LEN) dr[g0]     = hi0;
                    if ((unsigned)(g0 + 1) < (unsigned)LEN) dr[g0 + 1] = hi1;
                }
            }
        }
    }
    __syncthreads();

    level_pair_eo<16, 65541, 90, 4196224, false>(e1, o1, e2, o2, out, c, r, tid);  // d2
    __syncthreads();
    level_pair_eo< 8, 32774, 42, 2098688, false>(e2, o2, e3, o3, out, c, r, tid);  // d3
    __syncthreads();
    level_pair_eo< 4, 16390, 18, 1049728, false>(e3, o3, e4, o4, out, c, r, tid);  // d4
    __syncthreads();
    level_pair_eo< 2,  8198,  6,  525056, false>(e4, o4, e5, o5, out, c, r, tid);  // d5
    __syncthreads();
    level_pair_eo< 1,  4102,  0,  262528, true >(e5, o5, (float*)0, (float*)0,
                                                 out, c, r, tid);                   // d6 + a
}

extern "C" void kernel_launch(void* const* d_in, const int* in_sizes, int n_in,
                              void* d_out, int out_size) {
    const float* x = (const float*)d_in[0];
    float* out = (float*)d_out;
    const int rows = in_sizes[0] / 262144;          // 64
    const int chunks = (4102 + TT - 1) / TT;        // 65
    dim3 grid(chunks, rows);
    dwt6_fused_kernel<<<grid, TPB>>>(x, out);
}